// round 13
// baseline (speedup 1.0000x reference)
#include <cuda_runtime.h>
#include <cuda_fp16.h>
#include <cstdint>

#define NXS 32768
#define NH  1024

constexpr int BM = 128, BN = 128, BK = 64;               // BK in halves
constexpr int LDSW = 72;                  // halves; 144B stride (16 mod 128 -> LDSM conflict-free)
constexpr int TILE_H = BM * LDSW;         // 9216 halves
constexpr int TILE_BYTES = TILE_H * 2;    // 18432 B
constexpr int STAGE_BYTES = 2 * TILE_BYTES;               // A + B = 36864 B
constexpr size_t SMEM_BYTES = (size_t)3 * STAGE_BYTES;    // 110592 (x2 CTAs fits)

// ---------------- scratch (device globals: no allocation allowed) ----------
__device__ __half g_z1h[(size_t)NXS * NH];   // A of GEMM1: fp16(z1^2)
__device__ __half g_s1h[(size_t)NXS * NH];   // fp16(z1*(1-z1^2))
__device__ __half g_gh [(size_t)NXS * NH];   // A of GEMM2: fp16(g)
__device__ __half g_w2a[NH * NH];            // B of GEMM1: fp16(w2)      [i][m]
__device__ __half g_w2b[NH * NH];            // B of GEMM2: fp16(2*w2^T)  [m][i]
__device__ float  g_ypart[(size_t)NXS * 8];
__device__ float  g_dpart[(size_t)4 * NXS * 8];

// ---------------- helpers --------------------------------------------------
__device__ __forceinline__ void cp16u(uint32_t saddr, const void* g) {
    asm volatile("cp.async.cg.shared.global [%0], [%1], 16;" :: "r"(saddr), "l"(g));
}
__device__ __forceinline__ void ldsm4(uint32_t& r0, uint32_t& r1, uint32_t& r2,
                                      uint32_t& r3, uint32_t a) {
    asm volatile("ldmatrix.sync.aligned.m8n8.x4.shared.b16 {%0,%1,%2,%3}, [%4];"
                 : "=r"(r0), "=r"(r1), "=r"(r2), "=r"(r3) : "r"(a));
}
__device__ __forceinline__ float tanh_acc(float h) {
    float ah = fabsf(h);
    float e  = __expf(-2.0f * ah);
    float t  = 1.0f - 2.0f * e / (1.0f + e);
    return copysignf(t, h);
}
__device__ __forceinline__ float qred(float v) {
    v += __shfl_xor_sync(0xffffffffu, v, 1);
    v += __shfl_xor_sync(0xffffffffu, v, 2);
    return v;
}

// ---------------- weight prep: fp16 copy + scaled transpose ----------------
__global__ void prep_w_kernel(const float* __restrict__ w2) {
    __shared__ float tile[32][33];
    int m0 = blockIdx.x * 32, i0 = blockIdx.y * 32;
    int tx = threadIdx.x, ty = threadIdx.y;
#pragma unroll
    for (int r = ty; r < 32; r += 8) {
        float v = w2[(i0 + r) * NH + m0 + tx];
        g_w2a[(i0 + r) * NH + m0 + tx] = __float2half_rn(v);
        tile[r][tx] = v;
    }
    __syncthreads();
#pragma unroll
    for (int r = ty; r < 32; r += 8)
        g_w2b[(m0 + r) * NH + i0 + tx] = __float2half_rn(2.0f * tile[tx][r]);
}

// ---------------- layer 1: h1 -> z1^2 (fp16), s1 (fp16) --------------------
__global__ void prep_act_kernel(const float* __restrict__ x,
                                const float* __restrict__ w1,
                                const float* __restrict__ w1_2,
                                const float* __restrict__ b1) {
    int j = blockIdx.x;
    float x0 = x[2 * j], x1 = x[2 * j + 1];
    float xx0 = x0 * x0, xx1 = x1 * x1;
    size_t base = (size_t)j * NH;
#pragma unroll
    for (int i2 = threadIdx.x; i2 < 512; i2 += 256) {
        int i = 2 * i2;
        float4 wa = *(const float4*)(w1 + 2 * i);
        float4 wb = *(const float4*)(w1_2 + 2 * i);
        float2 bb = *(const float2*)(b1 + i);
        float h0 = xx0 * wa.x + xx1 * wa.y + x0 * wb.x + x1 * wb.y + bb.x;
        float h1 = xx0 * wa.z + xx1 * wa.w + x0 * wb.z + x1 * wb.w + bb.y;
        float z0 = tanh_acc(h0), z1 = tanh_acc(h1);
        float zz0 = z0 * z0, zz1 = z1 * z1;
        *(__half2*)(g_z1h + base + i) = __floats2half2_rn(zz0, zz1);
        *(__half2*)(g_s1h + base + i) = __floats2half2_rn(z0 * (1.f - zz0),
                                                          z1 * (1.f - zz1));
    }
}

// ---------------- fp16 GEMM (m16n8k16), 64x64 warp tiles -------------------
// 128 threads, 4 warps (2x2). C[M,N] = A[M,K] @ B[N,K]^T.
template <int MODE>
__global__ __launch_bounds__(128, 2) void gemm_kernel(
    const float* __restrict__ b2, const float* __restrict__ w3,
    const float* __restrict__ w1, const float* __restrict__ w1_2) {
    extern __shared__ __half smem[];
    const __half* A = (MODE == 0) ? g_z1h : g_gh;
    const __half* B = (MODE == 0) ? g_w2a : g_w2b;

    int bn = blockIdx.x, bm = blockIdx.y;
    int tid = threadIdx.x, lane = tid & 31, warp = tid >> 5;
    int wm = warp >> 1, wn = warp & 1;           // 64-row / 64-col groups
    int gid = lane >> 2, tig = lane & 3;

    float acc[4][8][4];
#pragma unroll
    for (int a = 0; a < 4; a++)
#pragma unroll
        for (int b = 0; b < 8; b++)
#pragma unroll
            for (int c = 0; c < 4; c++) acc[a][b][c] = 0.f;

    // ---- per-thread cp addressing (pointer-increment) ---------------------
    const uint32_t sb32 = (uint32_t)__cvta_generic_to_shared(smem);
    const int trow = tid >> 3;                 // 0..15
    const int tc8  = (tid & 7) * 8;            // halves
    const __half* aP = A + (size_t)(bm * BM + trow) * NH + tc8;
    const __half* bP = B + (size_t)(bn * BN + trow) * NH + tc8;
    const uint32_t sOff = (uint32_t)(trow * LDSW + tc8) * 2;
    constexpr uint32_t IT_S = (uint32_t)(16 * LDSW * 2);   // smem bytes per 16 rows
    constexpr size_t  IT_G = (size_t)16 * NH;              // gmem halves per 16 rows

    auto load_stage = [&](uint32_t sbase, const __half* a, const __half* b) {
#pragma unroll
        for (int it = 0; it < 8; ++it) {
            cp16u(sbase + sOff + it * IT_S, a + it * IT_G);
            cp16u(sbase + TILE_BYTES + sOff + it * IT_S, b + it * IT_G);
        }
    };

    // ---- ldmatrix per-lane byte offsets -----------------------------------
    int arow = wm * 64 + ((lane >> 3) & 1) * 8 + (lane & 7);
    int acol = ((lane >> 4) & 1) * 8;
    const uint32_t aoff = (uint32_t)((arow * LDSW + acol) * 2);   // + mt*16*LDSW*2
    int brow = wn * 64 + ((lane >> 3) & 1) * 8 + (lane & 7);
    int bcol = ((lane >> 4) & 1) * 8;
    const uint32_t boff = (uint32_t)TILE_BYTES + (uint32_t)((brow * LDSW + bcol) * 2);

    constexpr int KT = NH / BK;  // 16
    const uint32_t sEnd = sb32 + 2 * STAGE_BYTES;

    load_stage(sb32, aP, bP);
    asm volatile("cp.async.commit_group;");
    load_stage(sb32 + STAGE_BYTES, aP + BK, bP + BK);
    asm volatile("cp.async.commit_group;");
    aP += 2 * BK;  bP += 2 * BK;

    uint32_t cs = sb32;          // compute stage
    uint32_t pf = sEnd;          // prefetch stage

    for (int kb = 0; kb < KT; ++kb) {
        asm volatile("cp.async.wait_group 1;");
        __syncthreads();
        if (kb + 2 < KT) {
            load_stage(pf, aP, bP);
            aP += BK;  bP += BK;
        }
        asm volatile("cp.async.commit_group;");

        const uint32_t aa = cs + aoff, bb = cs + boff;
#pragma unroll
        for (int ks = 0; ks < BK / 16; ++ks) {           // 4 k16 steps
            const uint32_t kbyte = (uint32_t)(ks * 32);
            uint32_t af[4][4], bf[8][2];
#pragma unroll
            for (int mt = 0; mt < 4; ++mt)
                ldsm4(af[mt][0], af[mt][1], af[mt][2], af[mt][3],
                      aa + (uint32_t)(mt * 16 * LDSW * 2) + kbyte);
#pragma unroll
            for (int p = 0; p < 4; ++p)
                ldsm4(bf[2 * p][0], bf[2 * p + 1][0], bf[2 * p][1],
                      bf[2 * p + 1][1],
                      bb + (uint32_t)(p * 16 * LDSW * 2) + kbyte);
#pragma unroll
            for (int mt = 0; mt < 4; ++mt)
#pragma unroll
                for (int nt = 0; nt < 8; ++nt) {
                    asm volatile(
                        "mma.sync.aligned.m16n8k16.row.col.f32.f16.f16.f32 "
                        "{%0,%1,%2,%3}, {%4,%5,%6,%7}, {%8,%9}, {%0,%1,%2,%3};"
                        : "+f"(acc[mt][nt][0]), "+f"(acc[mt][nt][1]),
                          "+f"(acc[mt][nt][2]), "+f"(acc[mt][nt][3])
                        : "r"(af[mt][0]), "r"(af[mt][1]), "r"(af[mt][2]),
                          "r"(af[mt][3]), "r"(bf[nt][0]), "r"(bf[nt][1]));
                }
        }
        cs = (cs == sEnd) ? sb32 : cs + STAGE_BYTES;
        pf = (pf == sEnd) ? sb32 : pf + STAGE_BYTES;
    }
    asm volatile("cp.async.wait_group 0;");
    __syncthreads();  // smem free for epilogue

    float* smf = (float*)smem;
    if (MODE == 0) {
        // h2 -> z2 -> y row-partials + g (fp16 input of GEMM2)
        float* yacc = smf;  // 128 floats
        yacc[tid] = 0.f;
        __syncthreads();
#pragma unroll
        for (int mt = 0; mt < 4; ++mt) {
            float rs0 = 0.f, rs1 = 0.f;
            int r = bm * BM + wm * 64 + mt * 16 + gid;
            size_t ro  = (size_t)r * NH;
            size_t ro8 = ro + (size_t)8 * NH;
#pragma unroll
            for (int nt = 0; nt < 8; ++nt) {
                int n = bn * BN + wn * 64 + nt * 8 + 2 * tig;
                float b20 = b2[n], b21 = b2[n + 1];
                float w30 = w3[n], w31 = w3[n + 1];
                float z0 = tanh_acc(acc[mt][nt][0] + b20);
                float z1 = tanh_acc(acc[mt][nt][1] + b21);
                float z2 = tanh_acc(acc[mt][nt][2] + b20);
                float z3 = tanh_acc(acc[mt][nt][3] + b21);
                float zz0 = z0 * z0, zz1 = z1 * z1, zz2 = z2 * z2, zz3 = z3 * z3;
                rs0 += w30 * zz0 + w31 * zz1;
                rs1 += w30 * zz2 + w31 * zz3;
                *(__half2*)(g_gh + ro + n) =
                    __floats2half2_rn(2.f * w30 * z0 * (1.f - zz0),
                                      2.f * w31 * z1 * (1.f - zz1));
                *(__half2*)(g_gh + ro8 + n) =
                    __floats2half2_rn(2.f * w30 * z2 * (1.f - zz2),
                                      2.f * w31 * z3 * (1.f - zz3));
            }
            rs0 = qred(rs0);
            rs1 = qred(rs1);
            if (tig == 0) {                         // 2 adders/row (wn=0,1)
                atomicAdd(&yacc[wm * 64 + mt * 16 + gid], rs0);
                atomicAdd(&yacc[wm * 64 + mt * 16 + gid + 8], rs1);
            }
        }
        __syncthreads();
        g_ypart[(size_t)(bm * BM + tid) * 8 + bn] = yacc[tid];
    } else {
        // G * s1, then 4 weighted row-reductions (w1/w1_2 columns 0 and 1)
        float* w1s  = smf;         // 256 floats
        float* w12s = smf + 256;   // 256 floats
        float* dacc = smf + 512;   // 4*128 floats
        w1s[tid]        = w1[bn * 256 + tid];
        w1s[128 + tid]  = w1[bn * 256 + 128 + tid];
        w12s[tid]       = w1_2[bn * 256 + tid];
        w12s[128 + tid] = w1_2[bn * 256 + 128 + tid];
#pragma unroll
        for (int q = 0; q < 4; ++q) dacc[q * 128 + tid] = 0.f;
        __syncthreads();
#pragma unroll
        for (int mt = 0; mt < 4; ++mt) {
            float A0 = 0.f, B0 = 0.f, A1 = 0.f, B1 = 0.f;
            float A0h = 0.f, B0h = 0.f, A1h = 0.f, B1h = 0.f;
            int r = bm * BM + wm * 64 + mt * 16 + gid;
            size_t ro  = (size_t)r * NH;
            size_t ro8 = ro + (size_t)8 * NH;
#pragma unroll
            for (int nt = 0; nt < 8; ++nt) {
                int nl = wn * 64 + nt * 8 + 2 * tig;  // local m in [0,128)
                int n = bn * BN + nl;
                float2 s1a = __half22float2(*(const __half2*)(g_s1h + ro + n));
                float2 s1b = __half22float2(*(const __half2*)(g_s1h + ro8 + n));
                float P0 = acc[mt][nt][0] * s1a.x;
                float P1 = acc[mt][nt][1] * s1a.y;
                float P2 = acc[mt][nt][2] * s1b.x;
                float P3 = acc[mt][nt][3] * s1b.y;
                float wa0 = w1s[2 * nl],      wa1 = w1s[2 * nl + 1];
                float wb0 = w12s[2 * nl],     wb1 = w12s[2 * nl + 1];
                float wa0p = w1s[2 * nl + 2],  wa1p = w1s[2 * nl + 3];
                float wb0p = w12s[2 * nl + 2], wb1p = w12s[2 * nl + 3];
                A0 += P0 * wa0 + P1 * wa0p;   B0 += P0 * wb0 + P1 * wb0p;
                A1 += P0 * wa1 + P1 * wa1p;   B1 += P0 * wb1 + P1 * wb1p;
                A0h += P2 * wa0 + P3 * wa0p;  B0h += P2 * wb0 + P3 * wb0p;
                A1h += P2 * wa1 + P3 * wa1p;  B1h += P2 * wb1 + P3 * wb1p;
            }
            A0 = qred(A0);  B0 = qred(B0);  A1 = qred(A1);  B1 = qred(B1);
            A0h = qred(A0h); B0h = qred(B0h); A1h = qred(A1h); B1h = qred(B1h);
            if (tig == 0) {                         // 2 adders/row (wn=0,1)
                int rl = wm * 64 + mt * 16 + gid;
                atomicAdd(&dacc[rl],        A0);  atomicAdd(&dacc[128 + rl],       B0);
                atomicAdd(&dacc[256 + rl],  A1);  atomicAdd(&dacc[384 + rl],       B1);
                atomicAdd(&dacc[rl + 8],    A0h); atomicAdd(&dacc[128 + rl + 8],   B0h);
                atomicAdd(&dacc[256 + rl + 8], A1h); atomicAdd(&dacc[384 + rl + 8], B1h);
            }
        }
        __syncthreads();
        {
            size_t o = (size_t)(bm * BM + tid) * 8 + bn;
            g_dpart[o]                        = dacc[tid];
            g_dpart[(size_t)NXS * 8 + o]      = dacc[128 + tid];
            g_dpart[(size_t)2 * NXS * 8 + o]  = dacc[256 + tid];
            g_dpart[(size_t)3 * NXS * 8 + o]  = dacc[384 + tid];
        }
    }
}

// ---------------- finalize: fixed-order partial sums -> outputs ------------
__global__ void finalize_kernel(const float* __restrict__ x,
                                const float* __restrict__ b3,
                                float* __restrict__ out) {
    int j = blockIdx.x * 256 + threadIdx.x;
    float y = 0.f, A0 = 0.f, B0 = 0.f, A1 = 0.f, B1 = 0.f;
#pragma unroll
    for (int nb = 0; nb < 8; ++nb) {
        size_t o = (size_t)j * 8 + nb;
        y  += g_ypart[o];
        A0 += g_dpart[o];
        B0 += g_dpart[(size_t)NXS * 8 + o];
        A1 += g_dpart[(size_t)2 * NXS * 8 + o];
        B1 += g_dpart[(size_t)3 * NXS * 8 + o];
    }
    float x0 = x[2 * j], x1 = x[2 * j + 1];
    out[j]            = y + b3[0];          // y
    out[NXS + j]      = x1 * A1 + B1;       // dydx2
    out[2 * NXS + j]  = -(x0 * A0 + B0);    // -dydx1
}

// ---------------- launch ----------------------------------------------------
extern "C" void kernel_launch(void* const* d_in, const int* in_sizes, int n_in,
                              void* d_out, int out_size) {
    (void)in_sizes; (void)n_in; (void)out_size;
    const float* x    = (const float*)d_in[0];
    const float* w1   = (const float*)d_in[1];
    const float* w1_2 = (const float*)d_in[2];
    const float* b1   = (const float*)d_in[3];
    const float* w2   = (const float*)d_in[4];
    const float* b2   = (const float*)d_in[5];
    const float* w3   = (const float*)d_in[6];
    const float* b3   = (const float*)d_in[7];
    float* out = (float*)d_out;

    cudaFuncSetAttribute(gemm_kernel<0>, cudaFuncAttributeMaxDynamicSharedMemorySize,
                         (int)SMEM_BYTES);
    cudaFuncSetAttribute(gemm_kernel<1>, cudaFuncAttributeMaxDynamicSharedMemorySize,
                         (int)SMEM_BYTES);

    prep_w_kernel<<<dim3(32, 32), dim3(32, 8)>>>(w2);
    prep_act_kernel<<<NXS, 256>>>(x, w1, w1_2, b1);
    gemm_kernel<0><<<dim3(8, NXS / BM), 128, SMEM_BYTES>>>(b2, w3, w1, w1_2);
    gemm_kernel<1><<<dim3(8, NXS / BM), 128, SMEM_BYTES>>>(b2, w3, w1, w1_2);
    finalize_kernel<<<NXS / 256, 256>>>(x, b3, out);
}

// round 17
// speedup vs baseline: 1.1600x; 1.1600x over previous
#include <cuda_runtime.h>
#include <cuda_fp16.h>
#include <cstdint>

#define NXS 32768
#define NH  1024

constexpr int BM = 128, BN = 128, BK = 64, STAGES = 3;   // BK in halves
constexpr int LDSW = 72;                  // halves; 144B stride (16 mod 128 -> LDSM conflict-free)
constexpr int TILE_H = BM * LDSW;         // 9216 halves
constexpr int TILE_BYTES = TILE_H * 2;    // 18432 B
constexpr int STAGE_BYTES = 2 * TILE_BYTES;               // A + B = 36864 B
constexpr size_t SMEM_BYTES = (size_t)STAGES * STAGE_BYTES;  // 110592 (x2 CTAs fits)

// ---------------- scratch (device globals: no allocation allowed) ----------
__device__ __half g_z1h[(size_t)NXS * NH];   // A of GEMM1: fp16(z1^2)
__device__ __half g_s1h[(size_t)NXS * NH];   // fp16(z1*(1-z1^2))
__device__ __half g_gh [(size_t)NXS * NH];   // A of GEMM2: fp16(g)
__device__ __half g_w2a[NH * NH];            // B of GEMM1: fp16(w2)      [i][m]
__device__ __half g_w2b[NH * NH];            // B of GEMM2: fp16(2*w2^T)  [m][i]
__device__ float  g_ypart[(size_t)NXS * 8];
__device__ float  g_dpart[(size_t)4 * NXS * 8];

// ---------------- helpers --------------------------------------------------
__device__ __forceinline__ void cp16u(uint32_t saddr, const void* g) {
    asm volatile("cp.async.cg.shared.global [%0], [%1], 16;" :: "r"(saddr), "l"(g));
}
__device__ __forceinline__ void ldsm4(uint32_t& r0, uint32_t& r1, uint32_t& r2,
                                      uint32_t& r3, uint32_t a) {
    asm volatile("ldmatrix.sync.aligned.m8n8.x4.shared.b16 {%0,%1,%2,%3}, [%4];"
                 : "=r"(r0), "=r"(r1), "=r"(r2), "=r"(r3) : "r"(a));
}
__device__ __forceinline__ float tanh_acc(float h) {
    float ah = fabsf(h);
    float e  = __expf(-2.0f * ah);
    float t  = 1.0f - 2.0f * e / (1.0f + e);
    return copysignf(t, h);
}
__device__ __forceinline__ float qred(float v) {
    v += __shfl_xor_sync(0xffffffffu, v, 1);
    v += __shfl_xor_sync(0xffffffffu, v, 2);
    return v;
}

// ---------------- weight prep: fp16 copy + scaled transpose ----------------
__global__ void prep_w_kernel(const float* __restrict__ w2) {
    __shared__ float tile[32][33];
    int m0 = blockIdx.x * 32, i0 = blockIdx.y * 32;
    int tx = threadIdx.x, ty = threadIdx.y;
#pragma unroll
    for (int r = ty; r < 32; r += 8) {
        float v = w2[(i0 + r) * NH + m0 + tx];
        g_w2a[(i0 + r) * NH + m0 + tx] = __float2half_rn(v);
        tile[r][tx] = v;
    }
    __syncthreads();
#pragma unroll
    for (int r = ty; r < 32; r += 8)
        g_w2b[(m0 + r) * NH + i0 + tx] = __float2half_rn(2.0f * tile[tx][r]);
}

// ---------------- layer 1: h1 -> z1^2 (fp16), s1 (fp16) --------------------
__global__ void prep_act_kernel(const float* __restrict__ x,
                                const float* __restrict__ w1,
                                const float* __restrict__ w1_2,
                                const float* __restrict__ b1) {
    int j = blockIdx.x;
    float x0 = x[2 * j], x1 = x[2 * j + 1];
    float xx0 = x0 * x0, xx1 = x1 * x1;
    size_t base = (size_t)j * NH;
#pragma unroll
    for (int i2 = threadIdx.x; i2 < 512; i2 += 256) {
        int i = 2 * i2;
        float4 wa = *(const float4*)(w1 + 2 * i);
        float4 wb = *(const float4*)(w1_2 + 2 * i);
        float2 bb = *(const float2*)(b1 + i);
        float h0 = xx0 * wa.x + xx1 * wa.y + x0 * wb.x + x1 * wb.y + bb.x;
        float h1 = xx0 * wa.z + xx1 * wa.w + x0 * wb.z + x1 * wb.w + bb.y;
        float z0 = tanh_acc(h0), z1 = tanh_acc(h1);
        float zz0 = z0 * z0, zz1 = z1 * z1;
        *(__half2*)(g_z1h + base + i) = __floats2half2_rn(zz0, zz1);
        *(__half2*)(g_s1h + base + i) = __floats2half2_rn(z0 * (1.f - zz0),
                                                          z1 * (1.f - zz1));
    }
}

// ---------------- fp16 GEMM (m16n8k16), mode-specific epilogue -------------
// C[M,N] = A[M,K] @ B[N,K]^T  (both K-contiguous halves), M=32768, N=K=1024.
template <int MODE>
__global__ __launch_bounds__(256, 2) void gemm_kernel(
    const float* __restrict__ b2, const float* __restrict__ w3,
    const float* __restrict__ w1, const float* __restrict__ w1_2) {
    extern __shared__ __half smem[];
    const __half* A = (MODE == 0) ? g_z1h : g_gh;
    const __half* B = (MODE == 0) ? g_w2a : g_w2b;

    int bn = blockIdx.x, bm = blockIdx.y;
    int tid = threadIdx.x, lane = tid & 31, warp = tid >> 5;
    int wm = warp >> 1, wn = warp & 1;
    int gid = lane >> 2, tig = lane & 3;

    float acc[2][8][4];
#pragma unroll
    for (int a = 0; a < 2; a++)
#pragma unroll
        for (int b = 0; b < 8; b++)
#pragma unroll
            for (int c = 0; c < 4; c++) acc[a][b][c] = 0.f;

    // ---- per-thread cp addressing (pointer-increment) ---------------------
    const uint32_t sb32 = (uint32_t)__cvta_generic_to_shared(smem);
    const int trow = tid >> 3;                 // 0..31
    const int tc8  = (tid & 7) * 8;            // halves
    const __half* aP = A + (size_t)(bm * BM + trow) * NH + tc8;
    const __half* bP = B + (size_t)(bn * BN + trow) * NH + tc8;
    const uint32_t sOff = (uint32_t)(trow * LDSW + tc8) * 2;
    constexpr uint32_t IT_S = (uint32_t)(32 * LDSW * 2);   // smem bytes per 32 rows
    constexpr size_t  IT_G = (size_t)32 * NH;              // gmem halves per 32 rows

    auto load_stage = [&](uint32_t sbase, const __half* a, const __half* b) {
#pragma unroll
        for (int it = 0; it < 4; ++it) {
            cp16u(sbase + sOff + it * IT_S, a + it * IT_G);
            cp16u(sbase + TILE_BYTES + sOff + it * IT_S, b + it * IT_G);
        }
    };

    // ---- ldmatrix per-lane byte offsets -----------------------------------
    // A x4: quad = (rows0-7/k0-7, rows8-15/k0-7, rows0-7/k8-15, rows8-15/k8-15)
    //       = (a0,a1,a2,a3) consecutive — matches HMMA A quad directly.
    int arow = wm * 32 + ((lane >> 3) & 1) * 8 + (lane & 7);
    int acol = ((lane >> 4) & 1) * 8;
    const uint32_t aoff0 = (uint32_t)((arow * LDSW + acol) * 2);
    const uint32_t aoff1 = aoff0 + (uint32_t)(16 * LDSW * 2);
    // B x4: lane bit4 -> n-half, bit3 -> k-half, so the quad is
    //       (even.b0, even.b1, odd.b0, odd.b1): each MMA's (b0,b1) pair is
    //       CONSECUTIVE in the ldsm output quad -> no ptxas repacking MOVs.
    int brow = wn * 64 + ((lane >> 4) & 1) * 8 + (lane & 7);
    int bcol = ((lane >> 3) & 1) * 8;
    const uint32_t boff = (uint32_t)TILE_BYTES + (uint32_t)((brow * LDSW + bcol) * 2);

    constexpr int KT = NH / BK;  // 16
    const uint32_t sEnd = sb32 + 2 * STAGE_BYTES;

    // prologue: fill stages 0 and 1
    load_stage(sb32, aP, bP);
    asm volatile("cp.async.commit_group;");
    load_stage(sb32 + STAGE_BYTES, aP + BK, bP + BK);
    asm volatile("cp.async.commit_group;");
    aP += 2 * BK;  bP += 2 * BK;

    uint32_t cs = sb32;          // compute stage
    uint32_t pf = sEnd;          // prefetch stage

    for (int kb = 0; kb < KT; ++kb) {
        asm volatile("cp.async.wait_group 1;");
        __syncthreads();
        if (kb + 2 < KT) {
            load_stage(pf, aP, bP);
            aP += BK;  bP += BK;
        }
        asm volatile("cp.async.commit_group;");

        const uint32_t a0a = cs + aoff0, a1a = cs + aoff1, bba = cs + boff;
#pragma unroll
        for (int ks = 0; ks < BK / 16; ++ks) {           // 4 k16 steps
            const uint32_t kbyte = (uint32_t)(ks * 32);
            uint32_t af[2][4], bf[8][2];
            ldsm4(af[0][0], af[0][1], af[0][2], af[0][3], a0a + kbyte);
            ldsm4(af[1][0], af[1][1], af[1][2], af[1][3], a1a + kbyte);
#pragma unroll
            for (int p = 0; p < 4; ++p) {
                ldsm4(bf[2 * p][0], bf[2 * p][1], bf[2 * p + 1][0],
                      bf[2 * p + 1][1],
                      bba + (uint32_t)(p * 16 * LDSW * 2) + kbyte);
            }
#pragma unroll
            for (int mt = 0; mt < 2; ++mt)
#pragma unroll
                for (int nt = 0; nt < 8; ++nt) {
                    asm volatile(
                        "mma.sync.aligned.m16n8k16.row.col.f32.f16.f16.f32 "
                        "{%0,%1,%2,%3}, {%4,%5,%6,%7}, {%8,%9}, {%0,%1,%2,%3};"
                        : "+f"(acc[mt][nt][0]), "+f"(acc[mt][nt][1]),
                          "+f"(acc[mt][nt][2]), "+f"(acc[mt][nt][3])
                        : "r"(af[mt][0]), "r"(af[mt][1]), "r"(af[mt][2]),
                          "r"(af[mt][3]), "r"(bf[nt][0]), "r"(bf[nt][1]));
                }
        }
        cs = (cs == sEnd) ? sb32 : cs + STAGE_BYTES;
        pf = (pf == sEnd) ? sb32 : pf + STAGE_BYTES;
    }
    asm volatile("cp.async.wait_group 0;");
    __syncthreads();  // smem free for epilogue

    float* smf = (float*)smem;
    if (MODE == 0) {
        // h2 -> z2 -> y row-partials + g (fp16 input of GEMM2)
        float* yacc = smf;  // 128 floats
        if (tid < BM) yacc[tid] = 0.f;
        __syncthreads();
#pragma unroll
        for (int mt = 0; mt < 2; ++mt) {
            float rs0 = 0.f, rs1 = 0.f;
            int r = bm * BM + wm * 32 + mt * 16 + gid;
            size_t ro  = (size_t)r * NH;
            size_t ro8 = ro + (size_t)8 * NH;
#pragma unroll
            for (int nt = 0; nt < 8; ++nt) {
                int n = bn * BN + wn * 64 + nt * 8 + 2 * tig;
                float b20 = b2[n], b21 = b2[n + 1];
                float w30 = w3[n], w31 = w3[n + 1];
                float z0 = tanh_acc(acc[mt][nt][0] + b20);
                float z1 = tanh_acc(acc[mt][nt][1] + b21);
                float z2 = tanh_acc(acc[mt][nt][2] + b20);
                float z3 = tanh_acc(acc[mt][nt][3] + b21);
                float zz0 = z0 * z0, zz1 = z1 * z1, zz2 = z2 * z2, zz3 = z3 * z3;
                rs0 += w30 * zz0 + w31 * zz1;
                rs1 += w30 * zz2 + w31 * zz3;
                *(__half2*)(g_gh + ro + n) =
                    __floats2half2_rn(2.f * w30 * z0 * (1.f - zz0),
                                      2.f * w31 * z1 * (1.f - zz1));
                *(__half2*)(g_gh + ro8 + n) =
                    __floats2half2_rn(2.f * w30 * z2 * (1.f - zz2),
                                      2.f * w31 * z3 * (1.f - zz3));
            }
            rs0 = qred(rs0);
            rs1 = qred(rs1);
            if (tig == 0) {
                atomicAdd(&yacc[wm * 32 + mt * 16 + gid], rs0);      // 2 adders/row
                atomicAdd(&yacc[wm * 32 + mt * 16 + gid + 8], rs1);
            }
        }
        __syncthreads();
        if (tid < BM) g_ypart[(size_t)(bm * BM + tid) * 8 + bn] = yacc[tid];
    } else {
        // G * s1, then 4 weighted row-reductions (w1/w1_2 columns 0 and 1)
        float* w1s  = smf;         // 256 floats
        float* w12s = smf + 256;   // 256 floats
        float* dacc = smf + 512;   // 4*128 floats
        w1s[tid]  = w1[bn * 256 + tid];
        w12s[tid] = w1_2[bn * 256 + tid];
        dacc[tid] = 0.f;
        dacc[256 + tid] = 0.f;
        __syncthreads();
#pragma unroll
        for (int mt = 0; mt < 2; ++mt) {
            float A0 = 0.f, B0 = 0.f, A1 = 0.f, B1 = 0.f;
            float A0h = 0.f, B0h = 0.f, A1h = 0.f, B1h = 0.f;
            int r = bm * BM + wm * 32 + mt * 16 + gid;
            size_t ro  = (size_t)r * NH;
            size_t ro8 = ro + (size_t)8 * NH;
#pragma unroll
            for (int nt = 0; nt < 8; ++nt) {
                int nl = wn * 64 + nt * 8 + 2 * tig;  // local m in [0,128)
                int n = bn * BN + nl;
                float2 s1a = __half22float2(*(const __half2*)(g_s1h + ro + n));
                float2 s1b = __half22float2(*(const __half2*)(g_s1h + ro8 + n));
                float P0 = acc[mt][nt][0] * s1a.x;
                float P1 = acc[mt][nt][1] * s1a.y;
                float P2 = acc[mt][nt][2] * s1b.x;
                float P3 = acc[mt][nt][3] * s1b.y;
                float wa0 = w1s[2 * nl],      wa1 = w1s[2 * nl + 1];
                float wb0 = w12s[2 * nl],     wb1 = w12s[2 * nl + 1];
                float wa0p = w1s[2 * nl + 2],  wa1p = w1s[2 * nl + 3];
                float wb0p = w12s[2 * nl + 2], wb1p = w12s[2 * nl + 3];
                A0 += P0 * wa0 + P1 * wa0p;   B0 += P0 * wb0 + P1 * wb0p;
                A1 += P0 * wa1 + P1 * wa1p;   B1 += P0 * wb1 + P1 * wb1p;
                A0h += P2 * wa0 + P3 * wa0p;  B0h += P2 * wb0 + P3 * wb0p;
                A1h += P2 * wa1 + P3 * wa1p;  B1h += P2 * wb1 + P3 * wb1p;
            }
            A0 = qred(A0);  B0 = qred(B0);  A1 = qred(A1);  B1 = qred(B1);
            A0h = qred(A0h); B0h = qred(B0h); A1h = qred(A1h); B1h = qred(B1h);
            if (tig == 0) {
                int rl = wm * 32 + mt * 16 + gid;
                atomicAdd(&dacc[rl],        A0);  atomicAdd(&dacc[128 + rl],       B0);
                atomicAdd(&dacc[256 + rl],  A1);  atomicAdd(&dacc[384 + rl],       B1);
                atomicAdd(&dacc[rl + 8],    A0h); atomicAdd(&dacc[128 + rl + 8],   B0h);
                atomicAdd(&dacc[256 + rl + 8], A1h); atomicAdd(&dacc[384 + rl + 8], B1h);
            }
        }
        __syncthreads();
        if (tid < BM) {
            size_t o = (size_t)(bm * BM + tid) * 8 + bn;
            g_dpart[o]                        = dacc[tid];
            g_dpart[(size_t)NXS * 8 + o]      = dacc[128 + tid];
            g_dpart[(size_t)2 * NXS * 8 + o]  = dacc[256 + tid];
            g_dpart[(size_t)3 * NXS * 8 + o]  = dacc[384 + tid];
        }
    }
}

// ---------------- finalize: fixed-order partial sums -> outputs ------------
__global__ void finalize_kernel(const float* __restrict__ x,
                                const float* __restrict__ b3,
                                float* __restrict__ out) {
    int j = blockIdx.x * 256 + threadIdx.x;
    float y = 0.f, A0 = 0.f, B0 = 0.f, A1 = 0.f, B1 = 0.f;
#pragma unroll
    for (int nb = 0; nb < 8; ++nb) {
        size_t o = (size_t)j * 8 + nb;
        y  += g_ypart[o];
        A0 += g_dpart[o];
        B0 += g_dpart[(size_t)NXS * 8 + o];
        A1 += g_dpart[(size_t)2 * NXS * 8 + o];
        B1 += g_dpart[(size_t)3 * NXS * 8 + o];
    }
    float x0 = x[2 * j], x1 = x[2 * j + 1];
    out[j]            = y + b3[0];          // y
    out[NXS + j]      = x1 * A1 + B1;       // dydx2
    out[2 * NXS + j]  = -(x0 * A0 + B0);    // -dydx1
}

// ---------------- launch ----------------------------------------------------
extern "C" void kernel_launch(void* const* d_in, const int* in_sizes, int n_in,
                              void* d_out, int out_size) {
    (void)in_sizes; (void)n_in; (void)out_size;
    const float* x    = (const float*)d_in[0];
    const float* w1   = (const float*)d_in[1];
    const float* w1_2 = (const float*)d_in[2];
    const float* b1   = (const float*)d_in[3];
    const float* w2   = (const float*)d_in[4];
    const float* b2   = (const float*)d_in[5];
    const float* w3   = (const float*)d_in[6];
    const float* b3   = (const float*)d_in[7];
    float* out = (float*)d_out;

    cudaFuncSetAttribute(gemm_kernel<0>, cudaFuncAttributeMaxDynamicSharedMemorySize,
                         (int)SMEM_BYTES);
    cudaFuncSetAttribute(gemm_kernel<1>, cudaFuncAttributeMaxDynamicSharedMemorySize,
                         (int)SMEM_BYTES);

    prep_w_kernel<<<dim3(32, 32), dim3(32, 8)>>>(w2);
    prep_act_kernel<<<NXS, 256>>>(x, w1, w1_2, b1);
    gemm_kernel<0><<<dim3(8, NXS / BM), 256, SMEM_BYTES>>>(b2, w3, w1, w1_2);
    gemm_kernel<1><<<dim3(8, NXS / BM), 256, SMEM_BYTES>>>(b2, w3, w1, w1_2);
    finalize_kernel<<<NXS / 256, 256>>>(x, b3, out);
}